// round 12
// baseline (speedup 1.0000x reference)
#include <cuda_runtime.h>

#define BATCH  4096
#define TSTEPS 512
#define IN     3
#define HID    64
#define NCTA   304      // 2 CTAs per SM (152 SMs)
#define NTH    256
#define MAXR   14
#define HPAD   68       // h row stride (floats): 272B, 16B-aligned, 4-bank row shift

typedef unsigned long long ull;

// fma.rn.f32x2 on packed 64-bit registers (sm_100+): 2 fp32 FMAs / instr.
__device__ __forceinline__ ull ffma2u(ull a, ull b, ull c) {
    ull d;
    asm("fma.rn.f32x2 %0, %1, %2, %3;" : "=l"(d) : "l"(a), "l"(b), "l"(c));
    return d;
}
__device__ __forceinline__ ull addf32x2(ull a, ull b) {
    ull d;
    asm("add.rn.f32x2 %0, %1, %2;" : "=l"(d) : "l"(a), "l"(b));
    return d;
}
__device__ __forceinline__ float f2sum(ull v) {
    float lo, hi;
    asm("mov.b64 {%0, %1}, %2;" : "=f"(lo), "=f"(hi) : "l"(v));
    return lo + hi;
}
__device__ __forceinline__ float fast_rcp(float x) {
    float r;
    asm("rcp.approx.f32 %0, %1;" : "=f"(r) : "f"(x));
    return r;
}
__device__ __forceinline__ float fast_ex2(float x) {
    float r;
    asm("ex2.approx.f32 %0, %1;" : "=f"(r) : "f"(x));
    return r;
}
#define L2E 1.4426950408889634f

__global__ void __launch_bounds__(NTH, 2)
lstm_fused_kernel(const float* __restrict__ x,
                  const float* __restrict__ W_ih,
                  const float* __restrict__ W_hh,
                  const float* __restrict__ b_ih,
                  const float* __restrict__ b_hh,
                  const float* __restrict__ W_dec,
                  const float* __restrict__ b_dec,
                  float* __restrict__ out)
{
    __shared__ __align__(16) float hbuf[2][MAXR * HPAD];  // ping-pong h
    __shared__ __align__(16) float xbuf[2][MAXR * 4];     // ping-pong x_t
    __shared__ __align__(16) float wdec_s[IN][HID];
    __shared__ float bdec_s[IN];

    const int tid = threadIdx.x;
    const int bid = blockIdx.x;

    // batch-row distribution: 4096 = 144*14 + 160*13 over 304 CTAs
    const int BASE = BATCH / NCTA;                 // 13
    const int REM  = BATCH - BASE * NCTA;          // 144
    const int rows = BASE + (bid < REM ? 1 : 0);
    const int b0   = bid * BASE + min(bid, REM);

    // Gate-complete lane layout: warp w covers h in [8w, 8w+8).
    // lane = kq*8 + lane3: lane owns all 4 gate cols of h = 8w+lane3,
    // restricted to K-quarter kq (chunks 4i+kq, i=0..3; 4 floats per chunk).
    const int warp  = tid >> 5;
    const int lane  = tid & 31;
    const int lane3 = lane & 7;
    const int kq    = lane >> 3;
    const int hcol  = warp * 8 + lane3;
    const int jact  = hcol + 64 * kq;      // the gate column this lane activates

    // Resident weights: 4 gates x 16 K-floats = 64 fp32 = 32 ull regs.
    ull w[4][8];
    #pragma unroll
    for (int g = 0; g < 4; g++) {
        const float* wr = W_hh + (hcol + 64 * g) * HID;
        #pragma unroll
        for (int i = 0; i < 4; i++) {
            ulonglong2 v = *reinterpret_cast<const ulonglong2*>(wr + (4 * i + kq) * 4);
            w[g][2 * i] = v.x;  w[g][2 * i + 1] = v.y;
        }
    }
    // Uniform activation: act = ka * rcp(1 + ex2(m)) + kb, m = tot*s + xa_s.
    // kq==2 (g gate) -> tanh; else sigmoid.
    const float s_  = (kq == 2) ? (2.0f * L2E) : (-L2E);
    const float ka_ = (kq == 2) ? -2.0f : 1.0f;
    const float kb_ = (kq == 2) ?  1.0f : 0.0f;
    // Pre-scaled x weights/bias for this lane's gate column.
    const float wi0 = W_ih[jact * IN + 0] * s_;
    const float wi1 = W_ih[jact * IN + 1] * s_;
    const float wi2 = W_ih[jact * IN + 2] * s_;
    const float bias_s = (b_ih[jact] + b_hh[jact]) * s_;

    // decode weights to smem
    if (tid < IN * HID) wdec_s[tid / HID][tid % HID] = W_dec[tid];
    if (tid < IN)       bdec_s[tid] = b_dec[tid];

    // zero h buffer 0 (h_{-1} = 0)
    for (int i = tid; i < MAXR * HPAD; i += NTH) hbuf[0][i] = 0.0f;

    // per-(row,h) cell state, replicated across the 4 kq lanes (consistent).
    float c[MAXR];
    #pragma unroll
    for (int ri = 0; ri < MAXR; ri++) c[ri] = 0.0f;

    // (r, lane) mapping for x-staging and decode: tid < rows*3 (<=42)
    const bool d_valid = (tid < rows * IN);
    const int  d_r = tid / IN;
    const int  d_o = tid - d_r * IN;
    const size_t xo_base = ((size_t)(b0 + d_r) * TSTEPS) * IN + d_o;

    if (d_valid) xbuf[0][d_r * 4 + d_o] = x[xo_base];   // stage x_0

    __syncthreads();

    float* hcur  = &hbuf[0][0];   // h_{t-1}
    float* hnext = &hbuf[1][0];   // h_t (written this step)

    for (int t = 0; t < TSTEPS; t++) {
        const float* xs = &xbuf[t & 1][0];
        #pragma unroll
        for (int ri = 0; ri < MAXR; ri++) {
            if (ri < rows) {
                float4 xv = *reinterpret_cast<const float4*>(&xs[ri * 4]);
                float xa = fmaf(xv.z, wi2, fmaf(xv.y, wi1, fmaf(xv.x, wi0, bias_s)));

                const ulonglong2* hp =
                    reinterpret_cast<const ulonglong2*>(hcur + ri * HPAD);
                ull a0 = 0, a1 = 0, a2 = 0, a3 = 0;     // one chain per gate
                #pragma unroll
                for (int i = 0; i < 4; i++) {
                    ulonglong2 hv = hp[4 * i + kq];     // 4 contiguous 16B chunks/warp
                    a0 = ffma2u(hv.x, w[0][2 * i], a0);
                    a1 = ffma2u(hv.x, w[1][2 * i], a1);
                    a2 = ffma2u(hv.x, w[2][2 * i], a2);
                    a3 = ffma2u(hv.x, w[3][2 * i], a3);
                    a0 = ffma2u(hv.y, w[0][2 * i + 1], a0);
                    a1 = ffma2u(hv.y, w[1][2 * i + 1], a1);
                    a2 = ffma2u(hv.y, w[2][2 * i + 1], a2);
                    a3 = ffma2u(hv.y, w[3][2 * i + 1], a3);
                }
                float p0 = f2sum(a0), p1 = f2sum(a1), p2 = f2sum(a2), p3 = f2sum(a3);

                // Routed 2-level K-reduction: lane kq ends with full sum of gate kq.
                const bool q1 = (kq & 1), q2 = (kq & 2);
                float e0 = q1 ? p1 : p0, o0 = q1 ? p0 : p1;
                float e1 = q1 ? p3 : p2, o1 = q1 ? p2 : p3;
                float pk  = q2 ? e1 : e0;    // p[kq]
                float pk1 = q2 ? o1 : o0;    // p[kq^1]
                float pk2 = q2 ? e0 : e1;    // p[kq^2]
                float pk3 = q2 ? o0 : o1;    // p[kq^3]
                float A  = pk  + __shfl_xor_sync(0xffffffffu, pk1, 8);
                float Bv = pk2 + __shfl_xor_sync(0xffffffffu, pk3, 8);
                float tot = A + __shfl_xor_sync(0xffffffffu, Bv, 16);

                // activation (exactly one per lane)
                float m   = fmaf(tot, s_, xa);
                float y   = fast_rcp(1.0f + fast_ex2(m));
                float act = fmaf(ka_, y, kb_);

                // gather i,f,g,o for h = hcol (all lanes get same values)
                float ai = __shfl_sync(0xffffffffu, act, lane3);
                float af = __shfl_sync(0xffffffffu, act, lane3 + 8);
                float ag = __shfl_sync(0xffffffffu, act, lane3 + 16);
                float ao = __shfl_sync(0xffffffffu, act, lane3 + 24);

                float cn = fmaf(af, c[ri], ai * ag);
                c[ri] = cn;
                float y2 = fast_rcp(1.0f + fast_ex2(cn * (2.0f * L2E)));
                float th = fmaf(-2.0f, y2, 1.0f);
                float hn = ao * th;
                if (lane < 8) hnext[ri * HPAD + hcol] = hn;   // predicated STS
            }
        }

        // decode out[t-1] from hcur = h_{t-1}; prefetch x_{t+1}
        if (d_valid) {
            if (t > 0) {
                const ulonglong2* hp =
                    reinterpret_cast<const ulonglong2*>(hcur + d_r * HPAD);
                const ulonglong2* wp =
                    reinterpret_cast<const ulonglong2*>(wdec_s[d_o]);
                ull a0 = 0, a1 = 0;
                #pragma unroll
                for (int i = 0; i < 16; i++) {
                    ulonglong2 hv = hp[i];
                    ulonglong2 wv = wp[i];
                    a0 = ffma2u(hv.x, wv.x, a0);
                    a1 = ffma2u(hv.y, wv.y, a1);
                }
                out[xo_base + (size_t)(t - 1) * IN] = bdec_s[d_o] + f2sum(addf32x2(a0, a1));
            }
            if (t + 1 < TSTEPS)
                xbuf[(t + 1) & 1][d_r * 4 + d_o] = x[xo_base + (size_t)(t + 1) * IN];
        }

        __syncthreads();          // h_t complete; xbuf staged
        float* tmp = hcur; hcur = hnext; hnext = tmp;
    }

    // final decode: out[T-1] from hcur = h_{T-1}
    if (d_valid) {
        const ulonglong2* hp = reinterpret_cast<const ulonglong2*>(hcur + d_r * HPAD);
        const ulonglong2* wp = reinterpret_cast<const ulonglong2*>(wdec_s[d_o]);
        ull a0 = 0, a1 = 0;
        #pragma unroll
        for (int i = 0; i < 16; i++) {
            ulonglong2 hv = hp[i];
            ulonglong2 wv = wp[i];
            a0 = ffma2u(hv.x, wv.x, a0);
            a1 = ffma2u(hv.y, wv.y, a1);
        }
        out[xo_base + (size_t)(TSTEPS - 1) * IN] = bdec_s[d_o] + f2sum(addf32x2(a0, a1));
    }
}

extern "C" void kernel_launch(void* const* d_in, const int* in_sizes, int n_in,
                              void* d_out, int out_size)
{
    (void)in_sizes; (void)n_in; (void)out_size;
    const float* x     = (const float*)d_in[0];
    const float* W_ih  = (const float*)d_in[1];
    const float* W_hh  = (const float*)d_in[2];
    const float* b_ih  = (const float*)d_in[3];
    const float* b_hh  = (const float*)d_in[4];
    const float* W_dec = (const float*)d_in[5];
    const float* b_dec = (const float*)d_in[6];
    float* out = (float*)d_out;

    lstm_fused_kernel<<<NCTA, NTH>>>(x, W_ih, W_hh, b_ih, b_hh, W_dec, b_dec, out);
}